// round 9
// baseline (speedup 1.0000x reference)
#include <cuda_runtime.h>

#define NUM_NODES 1000000
#define NUM_EDGES 16000000
#define F  6
#define FP 8                // padded row: 32B
#define SCAN_BLK 1024
#define NBLK ((NUM_NODES + SCAN_BLK - 1) / SCAN_BLK)   // 977
#define GTHREADS 256        // gather block threads
#define GNODES   128        // nodes per gather block (one lane-pair per node)
#define SMEM_EDGES 4096     // staged capacity (mean 2048, >40 sigma margin)

// Scratch (device globals; no allocation anywhere).
__device__ __align__(128) float g_x8 [NUM_NODES * FP];
__device__ __align__(128) float g_h8 [NUM_NODES * FP];
__device__ __align__(128) int   g_sorted[NUM_EDGES];
__device__ __align__(128) int   g_cnt   [NUM_NODES];
__device__ __align__(128) int   g_rowst [NUM_NODES];
__device__ __align__(128) int   g_cursor[NUM_NODES];
__device__ __align__(128) int   g_bsum  [NBLK];
__device__ int g_idx_is32;

// ---------------------------------------------------------------------------
__global__ void detect_kernel(const long long* __restrict__ ei) {
    __shared__ int bad;
    if (threadIdx.x == 0) bad = 0;
    __syncthreads();
    #pragma unroll
    for (int r = 0; r < 16; r++) {
        long long v = ei[threadIdx.x + r * 256];
        if ((unsigned long long)v >= (unsigned long long)NUM_NODES) bad = 1;
    }
    __syncthreads();
    if (threadIdx.x == 0) g_idx_is32 = bad;
}

// pad x, zero degree counters (no agg table needed anymore: no atomics).
__global__ void prep_kernel(const float* __restrict__ x) {
    int i = blockIdx.x * blockDim.x + threadIdx.x;
    if (i >= NUM_NODES) return;
    const float* xr = x + (size_t)i * F;
    float4* px = reinterpret_cast<float4*>(g_x8 + (size_t)i * FP);
    px[0] = make_float4(xr[0], xr[1], xr[2], xr[3]);
    px[1] = make_float4(xr[4], xr[5], 0.f, 0.f);
    g_cnt[i] = 0;
}

// ---------------------------------------------------------------------------
__global__ void hist_kernel(const void* __restrict__ ei) {
    int i = blockIdx.x * blockDim.x + threadIdx.x;
    if (i >= NUM_EDGES / 4) return;
    unsigned d[4];
    if (g_idx_is32) {
        const int* dst = (const int*)ei + NUM_EDGES;
        int4 dv = __ldcs(reinterpret_cast<const int4*>(dst) + i);
        d[0] = dv.x; d[1] = dv.y; d[2] = dv.z; d[3] = dv.w;
    } else {
        const long long* dst = (const long long*)ei + NUM_EDGES;
        longlong2 d0 = __ldcs(reinterpret_cast<const longlong2*>(dst) + 2 * i);
        longlong2 d1 = __ldcs(reinterpret_cast<const longlong2*>(dst) + 2 * i + 1);
        d[0] = (unsigned)d0.x; d[1] = (unsigned)d0.y;
        d[2] = (unsigned)d1.x; d[3] = (unsigned)d1.y;
    }
    #pragma unroll
    for (int e = 0; e < 4; e++)
        if (d[e] < NUM_NODES) atomicAdd(&g_cnt[d[e]], 1);
}

// ---------------------------------------------------------------------------
__global__ void scan1_kernel() {
    __shared__ int s[SCAN_BLK];
    int t = threadIdx.x;
    int gid = blockIdx.x * SCAN_BLK + t;
    int v = (gid < NUM_NODES) ? g_cnt[gid] : 0;
    s[t] = v;
    for (int off = 1; off < SCAN_BLK; off <<= 1) {
        __syncthreads();
        int add = (t >= off) ? s[t - off] : 0;
        __syncthreads();
        s[t] += add;
    }
    __syncthreads();
    if (gid < NUM_NODES) g_rowst[gid] = s[t] - v;
    if (t == SCAN_BLK - 1) g_bsum[blockIdx.x] = s[t];
}

__global__ void scan2_kernel() {
    __shared__ int s[SCAN_BLK];
    int t = threadIdx.x;
    int v = (t < NBLK) ? g_bsum[t] : 0;
    s[t] = v;
    for (int off = 1; off < SCAN_BLK; off <<= 1) {
        __syncthreads();
        int add = (t >= off) ? s[t - off] : 0;
        __syncthreads();
        s[t] += add;
    }
    __syncthreads();
    if (t < NBLK) g_bsum[t] = s[t] - v;
}

__global__ void scan3_kernel() {
    int gid = blockIdx.x * SCAN_BLK + threadIdx.x;
    if (gid >= NUM_NODES) return;
    int r = g_rowst[gid] + g_bsum[blockIdx.x];
    g_rowst[gid]  = r;
    g_cursor[gid] = r;
}

// ---------------------------------------------------------------------------
__global__ void reorder_kernel(const void* __restrict__ ei) {
    int i = blockIdx.x * blockDim.x + threadIdx.x;
    if (i >= NUM_EDGES / 4) return;
    unsigned s[4], d[4];
    if (g_idx_is32) {
        const int* src = (const int*)ei;
        const int* dst = src + NUM_EDGES;
        int4 sv = __ldcs(reinterpret_cast<const int4*>(src) + i);
        int4 dv = __ldcs(reinterpret_cast<const int4*>(dst) + i);
        s[0] = sv.x; s[1] = sv.y; s[2] = sv.z; s[3] = sv.w;
        d[0] = dv.x; d[1] = dv.y; d[2] = dv.z; d[3] = dv.w;
    } else {
        const long long* src = (const long long*)ei;
        const long long* dst = src + NUM_EDGES;
        longlong2 s0 = __ldcs(reinterpret_cast<const longlong2*>(src) + 2 * i);
        longlong2 s1 = __ldcs(reinterpret_cast<const longlong2*>(src) + 2 * i + 1);
        longlong2 d0 = __ldcs(reinterpret_cast<const longlong2*>(dst) + 2 * i);
        longlong2 d1 = __ldcs(reinterpret_cast<const longlong2*>(dst) + 2 * i + 1);
        s[0] = (unsigned)s0.x; s[1] = (unsigned)s0.y; s[2] = (unsigned)s1.x; s[3] = (unsigned)s1.y;
        d[0] = (unsigned)d0.x; d[1] = (unsigned)d0.y; d[2] = (unsigned)d1.x; d[3] = (unsigned)d1.y;
    }
    #pragma unroll
    for (int e = 0; e < 4; e++) {
        if (s[e] < NUM_NODES && d[e] < NUM_NODES) {
            int p = atomicAdd(&g_cursor[d[e]], 1);
            g_sorted[p] = (int)s[e];
        }
    }
}

// ---------------------------------------------------------------------------
// Pair-laned fused gather + transform. One lane PAIR per node: lane h loads
// 16B half h of each in-neighbor row (pair shares one 128B line -> 1 load-
// wavefront per edge), accumulates in registers (NO atomics). Even lane
// collects the odd half via 2 shfls and computes the 6x6 transform.
// PHASE 0: x8 -> h8.  PHASE 1: h8 -> argmax/one-hot -> out.
// ---------------------------------------------------------------------------
template <int PHASE>
__global__ void gather_kernel(const float* __restrict__ Wrel,
                              const float* __restrict__ Wroot,
                              const float* __restrict__ b,
                              float* __restrict__ out) {
    __shared__ float swr[36], swo[36], sb[6];
    __shared__ int   s_edges[SMEM_EDGES];
    __shared__ int   s_info[2];     // bstart, total (-1 = fallback)

    int t = threadIdx.x;
    if (t < 36)        swr[t]      = Wrel[t];
    else if (t < 72)   swo[t - 36] = Wroot[t - 36];
    else if (t < 78)   sb[t - 72]  = b[t - 72];

    int pair = t >> 1;
    int h    = t & 1;
    int lane = t & 31;
    int n0   = blockIdx.x * GNODES;
    int n    = n0 + pair;
    bool valid = (n < NUM_NODES);
    int nc   = valid ? n : (NUM_NODES - 1);   // clamped for safe loads

    int myStart = g_rowst[nc];
    int myDeg   = valid ? g_cnt[nc] : 0;

    if (t == 0) {
        int nL = min(n0 + GNODES, NUM_NODES) - 1;
        int bstart = g_rowst[n0];
        int total  = g_rowst[nL] + g_cnt[nL] - bstart;
        s_info[0] = bstart;
        s_info[1] = (total <= SMEM_EDGES) ? total : -1;
    }
    __syncthreads();
    int bstart = s_info[0];
    int total  = s_info[1];

    if (total >= 0) {
        for (int k = t; k < total; k += GTHREADS)
            s_edges[k] = g_sorted[bstart + k];          // coalesced
    }
    __syncthreads();

    const float* feat = PHASE ? g_h8 : g_x8;
    // acc holds this lane's HALF: h=0 -> f0..f3 ; h=1 -> f4,f5,0,0
    float4 acc = make_float4(0.f, 0.f, 0.f, 0.f);

    if (total >= 0) {
        int off = myStart - bstart;
        int j = 0;
        for (; j + 1 < myDeg; j += 2) {                 // 2-way MLP
            int s0 = s_edges[off + j];
            int s1 = s_edges[off + j + 1];
            float4 v0 = *reinterpret_cast<const float4*>(feat + (size_t)s0 * FP + h * 4);
            float4 v1 = *reinterpret_cast<const float4*>(feat + (size_t)s1 * FP + h * 4);
            acc.x += v0.x + v1.x;  acc.y += v0.y + v1.y;
            acc.z += v0.z + v1.z;  acc.w += v0.w + v1.w;
        }
        if (j < myDeg) {
            int s0 = s_edges[off + j];
            float4 v0 = *reinterpret_cast<const float4*>(feat + (size_t)s0 * FP + h * 4);
            acc.x += v0.x; acc.y += v0.y; acc.z += v0.z; acc.w += v0.w;
        }
    } else {
        for (int j = 0; j < myDeg; j++) {               // fallback (never for uniform graphs)
            int s0 = g_sorted[myStart + j];
            float4 v0 = *reinterpret_cast<const float4*>(feat + (size_t)s0 * FP + h * 4);
            acc.x += v0.x; acc.y += v0.y; acc.z += v0.z; acc.w += v0.w;
        }
    }

    // even lane fetches odd lane's two live sums (f4,f5)
    float hi4 = __shfl_sync(0xFFFFFFFFu, acc.x, lane | 1);
    float hi5 = __shfl_sync(0xFFFFFFFFu, acc.y, lane | 1);

    if (h == 0 && valid) {
        float ag[6] = {acc.x, acc.y, acc.z, acc.w, hi4, hi5};

        const float* xr = feat + (size_t)n * FP;
        float4 x0 = *reinterpret_cast<const float4*>(xr);
        float2 x1 = *reinterpret_cast<const float2*>(xr + 4);
        float xv[6] = {x0.x, x0.y, x0.z, x0.w, x1.x, x1.y};

        float hh[6];
        #pragma unroll
        for (int k = 0; k < 6; k++) {
            float a = sb[k];
            #pragma unroll
            for (int m = 0; m < 6; m++) {
                a = fmaf(ag[m], swr[k * 6 + m], a);
                a = fmaf(xv[m], swo[k * 6 + m], a);
            }
            hh[k] = a;
        }

        if (PHASE == 0) {
            float4* ph = reinterpret_cast<float4*>(g_h8 + (size_t)n * FP);
            ph[0] = make_float4(hh[0], hh[1], hh[2], hh[3]);
            ph[1] = make_float4(hh[4], hh[5], 0.f, 0.f);
        } else {
            int best = 0; float bv = hh[0];
            #pragma unroll
            for (int k = 1; k < 6; k++)
                if (hh[k] > bv) { bv = hh[k]; best = k; }   // first-max = jnp.argmax
            float* po = out + (size_t)n * F;
            #pragma unroll
            for (int k = 0; k < 6; k++)
                po[k] = (k == best) ? 1.f : 0.f;
        }
    }
}

extern "C" void kernel_launch(void* const* d_in, const int* in_sizes, int n_in,
                              void* d_out, int out_size) {
    const float* x      = (const float*)d_in[0];
    const void*  ei     = d_in[1];
    const float* Wrel1  = (const float*)d_in[2];
    const float* Wroot1 = (const float*)d_in[3];
    const float* b1     = (const float*)d_in[4];
    const float* Wrel2  = (const float*)d_in[5];
    const float* Wroot2 = (const float*)d_in[6];
    const float* b2     = (const float*)d_in[7];
    float*       out    = (float*)d_out;

    const int BLK = 256;
    const int node_grid   = (NUM_NODES + BLK - 1) / BLK;
    const int quad_grid   = (NUM_EDGES / 4 + BLK - 1) / BLK;
    const int gather_grid = (NUM_NODES + GNODES - 1) / GNODES;   // 7813

    detect_kernel<<<1, 256>>>((const long long*)ei);
    prep_kernel<<<node_grid, BLK>>>(x);
    // CSR build (once; reused by both layers)
    hist_kernel<<<quad_grid, BLK>>>(ei);
    scan1_kernel<<<NBLK, SCAN_BLK>>>();
    scan2_kernel<<<1, SCAN_BLK>>>();
    scan3_kernel<<<NBLK, SCAN_BLK>>>();
    reorder_kernel<<<quad_grid, BLK>>>(ei);
    // Two pair-laned fused gather+transform layers (zero atomics)
    gather_kernel<0><<<gather_grid, GTHREADS>>>(Wrel1, Wroot1, b1, nullptr);
    gather_kernel<1><<<gather_grid, GTHREADS>>>(Wrel2, Wroot2, b2, out);
}

// round 10
// speedup vs baseline: 1.2720x; 1.2720x over previous
#include <cuda_runtime.h>

#define NUM_NODES 1000000
#define NUM_EDGES 16000000
#define F  6
#define FP 8   // padded feature width: 32B row = one L2 sector

// Scratch: device globals (no allocation allowed anywhere).
__device__ __align__(128) float g_x8 [NUM_NODES * FP];  // padded x (lanes 6,7 = 0)
__device__ __align__(128) float g_agg[NUM_NODES * FP];  // scatter-add accumulator
__device__ __align__(128) float g_h8 [NUM_NODES * FP];  // padded layer-1 output
__device__ int g_idx_is32;                              // 1 if edge_index is int32

// ---------------------------------------------------------------------------
// prep: pad x into g_x8, zero g_agg. Block 0 additionally detects the
// edge-index dtype (int64 indices < 1M always have zero high words).
// ---------------------------------------------------------------------------
__global__ void prep_kernel(const float* __restrict__ x,
                            const long long* __restrict__ ei) {
    if (blockIdx.x == 0) {
        __shared__ int bad;
        if (threadIdx.x == 0) bad = 0;
        __syncthreads();
        #pragma unroll
        for (int r = 0; r < 16; r++) {
            long long v = ei[threadIdx.x + r * 256];
            if ((unsigned long long)v >= (unsigned long long)NUM_NODES) bad = 1;
        }
        __syncthreads();
        if (threadIdx.x == 0) g_idx_is32 = bad;
    }
    int i = blockIdx.x * blockDim.x + threadIdx.x;
    if (i >= NUM_NODES) return;
    const float* xr = x + (size_t)i * F;
    float4* px = reinterpret_cast<float4*>(g_x8 + (size_t)i * FP);
    px[0] = make_float4(xr[0], xr[1], xr[2], xr[3]);
    px[1] = make_float4(xr[4], xr[5], 0.f, 0.f);
    float4 z = make_float4(0.f, 0.f, 0.f, 0.f);
    float4* pa = reinterpret_cast<float4*>(g_agg + (size_t)i * FP);
    pa[0] = z; pa[1] = z;
}

__device__ __forceinline__ void red_add_v4(float* p, float4 v) {
    asm volatile("red.global.add.v4.f32 [%0], {%1, %2, %3, %4};"
                 :: "l"(p), "f"(v.x), "f"(v.y), "f"(v.z), "f"(v.w) : "memory");
}

// ---------------------------------------------------------------------------
// Lane-paired edge scatter (R8 structure, proven 403us), plus shfl index
// sharing: even lane of a pair loads src[e], odd lane loads dst[e]; two
// shfls give both lanes both values -> HALF the index loads of R8.
// Work item = half-edge (item = 2e + h). 4 items/thread, grid-strided so
// lane pairs stay adjacent and h is fixed per thread (= gid & 1).
// ---------------------------------------------------------------------------
#define NITEMS (2 * NUM_EDGES)
#define ITEMS_PER_THREAD 4
#define SCAT_THREADS (NITEMS / ITEMS_PER_THREAD)   // 8M (exact multiple of 256)

template <int PHASE>
__global__ void scatter_kernel(const void* __restrict__ ei) {
    int gid = blockIdx.x * blockDim.x + threadIdx.x;
    if (gid >= SCAT_THREADS) return;                  // never taken (exact grid)
    const float* feat = (PHASE == 0) ? g_x8 : g_h8;
    const bool is32 = (g_idx_is32 != 0);
    const int lane = threadIdx.x & 31;
    const int h    = gid & 1;                         // fixed half per thread

    unsigned s[ITEMS_PER_THREAD], d[ITEMS_PER_THREAD];
    #pragma unroll
    for (int k = 0; k < ITEMS_PER_THREAD; k++) {
        int item = gid + k * SCAT_THREADS;            // parity preserved
        int e = item >> 1;                            // same e for both pair lanes
        unsigned my;
        if (is32) {
            const int* p = (h == 0) ? (const int*)ei
                                    : (const int*)ei + NUM_EDGES;
            my = (unsigned)__ldcs(p + e);
        } else {
            const long long* p = (h == 0) ? (const long long*)ei
                                          : (const long long*)ei + NUM_EDGES;
            my = (unsigned)__ldcs(p + e);
        }
        s[k] = __shfl_sync(0xFFFFFFFFu, my, lane & ~1);   // src from even lane
        d[k] = __shfl_sync(0xFFFFFFFFu, my, lane |  1);   // dst from odd lane
    }

    float4 v[ITEMS_PER_THREAD];
    bool ok[ITEMS_PER_THREAD];
    #pragma unroll
    for (int k = 0; k < ITEMS_PER_THREAD; k++) {
        ok[k] = (s[k] < NUM_NODES) && (d[k] < NUM_NODES);
        if (ok[k])
            v[k] = *(reinterpret_cast<const float4*>(feat + (size_t)s[k] * FP) + h);
    }
    #pragma unroll
    for (int k = 0; k < ITEMS_PER_THREAD; k++) {
        if (ok[k])
            red_add_v4(g_agg + (size_t)d[k] * FP + h * 4, v[k]);
    }
}

// ---------------------------------------------------------------------------
// per-node dense transform (proven structure, streaming loads).
// FINAL=false : write padded h into g_h8, re-zero g_agg for layer 2.
// FINAL=true  : argmax (first-max wins = jnp.argmax) -> one-hot.
// ---------------------------------------------------------------------------
template <bool FINAL>
__global__ void transform_kernel(const float* __restrict__ Wrel,
                                 const float* __restrict__ Wroot,
                                 const float* __restrict__ b,
                                 float* __restrict__ out) {
    __shared__ float swr[36], swo[36], sb[6];
    int t = threadIdx.x;
    if (t < 36)        swr[t]      = Wrel[t];
    else if (t < 72)   swo[t - 36] = Wroot[t - 36];
    else if (t < 78)   sb[t - 72]  = b[t - 72];
    __syncthreads();

    int i = blockIdx.x * blockDim.x + t;
    if (i >= NUM_NODES) return;

    const float* in_feat = FINAL ? g_h8 : g_x8;

    const float4* pa = reinterpret_cast<const float4*>(g_agg + (size_t)i * FP);
    float4 a0 = __ldcs(pa);     float4 a1 = __ldcs(pa + 1);
    const float4* px = reinterpret_cast<const float4*>(in_feat + (size_t)i * FP);
    float4 x0 = __ldcs(px);     float4 x1 = __ldcs(px + 1);

    float ag[6] = {a0.x, a0.y, a0.z, a0.w, a1.x, a1.y};
    float xv[6] = {x0.x, x0.y, x0.z, x0.w, x1.x, x1.y};

    float h[6];
    #pragma unroll
    for (int k = 0; k < 6; k++) {
        float acc = sb[k];
        #pragma unroll
        for (int j = 0; j < 6; j++) {
            acc = fmaf(ag[j], swr[k * 6 + j], acc);
            acc = fmaf(xv[j], swo[k * 6 + j], acc);
        }
        h[k] = acc;
    }

    if (!FINAL) {
        float4 z = make_float4(0.f, 0.f, 0.f, 0.f);
        float4* paw = reinterpret_cast<float4*>(g_agg + (size_t)i * FP);
        paw[0] = z; paw[1] = z;
        float4* ph = reinterpret_cast<float4*>(g_h8 + (size_t)i * FP);
        ph[0] = make_float4(h[0], h[1], h[2], h[3]);
        ph[1] = make_float4(h[4], h[5], 0.f, 0.f);
    } else {
        int best = 0; float bv = h[0];
        #pragma unroll
        for (int k = 1; k < 6; k++)
            if (h[k] > bv) { bv = h[k]; best = k; }
        float* po = out + (size_t)i * F;
        #pragma unroll
        for (int k = 0; k < 6; k++)
            po[k] = (k == best) ? 1.f : 0.f;
    }
}

extern "C" void kernel_launch(void* const* d_in, const int* in_sizes, int n_in,
                              void* d_out, int out_size) {
    const float* x      = (const float*)d_in[0];
    const void*  ei     = d_in[1];
    const float* Wrel1  = (const float*)d_in[2];
    const float* Wroot1 = (const float*)d_in[3];
    const float* b1     = (const float*)d_in[4];
    const float* Wrel2  = (const float*)d_in[5];
    const float* Wroot2 = (const float*)d_in[6];
    const float* b2     = (const float*)d_in[7];
    float*       out    = (float*)d_out;

    const int BLK = 256;
    const int node_grid = (NUM_NODES + BLK - 1) / BLK;
    const int scat_grid = SCAT_THREADS / BLK;          // exact

    // Layer 1
    prep_kernel<<<node_grid, BLK>>>(x, (const long long*)ei);
    scatter_kernel<0><<<scat_grid, BLK>>>(ei);
    transform_kernel<false><<<node_grid, BLK>>>(Wrel1, Wroot1, b1, nullptr);
    // Layer 2
    scatter_kernel<1><<<scat_grid, BLK>>>(ei);
    transform_kernel<true><<<node_grid, BLK>>>(Wrel2, Wroot2, b2, out);
}

// round 12
// speedup vs baseline: 1.2776x; 1.0044x over previous
#include <cuda_runtime.h>

#define NUM_NODES 1000000
#define NUM_EDGES 16000000
#define F  6
#define FP 8   // padded feature width: 32B row = one L2 sector

// Scratch: device globals (no allocation allowed anywhere).
__device__ __align__(128) float g_x8 [NUM_NODES * FP];  // padded x (lanes 6,7 = 0)
__device__ __align__(128) float g_agg[NUM_NODES * FP];  // scatter-add accumulator
__device__ __align__(128) float g_h8 [NUM_NODES * FP];  // padded layer-1 output
__device__ int g_idx_is32;                              // 1 if edge_index is int32

// ---------------------------------------------------------------------------
// prep: pad x into g_x8 (2 nodes/thread, vectorized 3x float4 reads), zero
// g_agg. Block 0 additionally detects the edge-index dtype.
// ---------------------------------------------------------------------------
__global__ void prep_kernel(const float* __restrict__ x,
                            const long long* __restrict__ ei) {
    if (blockIdx.x == 0) {
        __shared__ int bad;
        if (threadIdx.x == 0) bad = 0;
        __syncthreads();
        #pragma unroll
        for (int r = 0; r < 16; r++) {
            long long v = ei[threadIdx.x + r * 256];
            if ((unsigned long long)v >= (unsigned long long)NUM_NODES) bad = 1;
        }
        __syncthreads();
        if (threadIdx.x == 0) g_idx_is32 = bad;
    }
    int i = blockIdx.x * blockDim.x + threadIdx.x;    // node-pair id
    if (i >= NUM_NODES / 2) return;
    const float4* px = reinterpret_cast<const float4*>(x + (size_t)i * 12);
    float4 a = __ldcs(px);                             // x[2i][0..3]
    float4 bq = __ldcs(px + 1);                        // x[2i][4,5], x[2i+1][0,1]
    float4 c = __ldcs(px + 2);                         // x[2i+1][2..5]

    float4* po = reinterpret_cast<float4*>(g_x8 + (size_t)i * 2 * FP);
    po[0] = a;
    po[1] = make_float4(bq.x, bq.y, 0.f, 0.f);
    po[2] = make_float4(bq.z, bq.w, c.x, c.y);
    po[3] = make_float4(c.z, c.w, 0.f, 0.f);

    float4 z = make_float4(0.f, 0.f, 0.f, 0.f);
    float4* pa = reinterpret_cast<float4*>(g_agg + (size_t)i * 2 * FP);
    pa[0] = z; pa[1] = z; pa[2] = z; pa[3] = z;
}

__device__ __forceinline__ void red_add_v4(float* p, float4 v) {
    asm volatile("red.global.add.v4.f32 [%0], {%1, %2, %3, %4};"
                 :: "l"(p), "f"(v.x), "f"(v.y), "f"(v.z), "f"(v.w) : "memory");
}

// ---------------------------------------------------------------------------
// Lane-paired edge scatter (proven 170.6us/layer, ~96% of the RED-issue
// floor). Work item = half-edge (item = 2e + h). Even lane of a pair loads
// src[e], odd loads dst[e]; 2 shfls share both. Each lane loads 16B half h
// of the source row (pair shares one 128B line -> 1 gather wavefront/edge)
// and issues one red.v4 to half h of the accumulator row.
// ---------------------------------------------------------------------------
#define NITEMS (2 * NUM_EDGES)
#define ITEMS_PER_THREAD 4
#define SCAT_THREADS (NITEMS / ITEMS_PER_THREAD)   // 8M (exact multiple of 256)

template <int PHASE>
__global__ void scatter_kernel(const void* __restrict__ ei) {
    int gid = blockIdx.x * blockDim.x + threadIdx.x;
    const float* feat = (PHASE == 0) ? g_x8 : g_h8;
    const bool is32 = (g_idx_is32 != 0);
    const int lane = threadIdx.x & 31;
    const int h    = gid & 1;                         // fixed half per thread

    unsigned s[ITEMS_PER_THREAD], d[ITEMS_PER_THREAD];
    #pragma unroll
    for (int k = 0; k < ITEMS_PER_THREAD; k++) {
        int item = gid + k * SCAT_THREADS;            // parity preserved
        int e = item >> 1;                            // same e for both pair lanes
        unsigned my;
        if (is32) {
            const int* p = (h == 0) ? (const int*)ei
                                    : (const int*)ei + NUM_EDGES;
            my = (unsigned)__ldcs(p + e);
        } else {
            const long long* p = (h == 0) ? (const long long*)ei
                                          : (const long long*)ei + NUM_EDGES;
            my = (unsigned)__ldcs(p + e);
        }
        s[k] = __shfl_sync(0xFFFFFFFFu, my, lane & ~1);   // src from even lane
        d[k] = __shfl_sync(0xFFFFFFFFu, my, lane |  1);   // dst from odd lane
    }

    float4 v[ITEMS_PER_THREAD];
    bool ok[ITEMS_PER_THREAD];
    #pragma unroll
    for (int k = 0; k < ITEMS_PER_THREAD; k++) {
        ok[k] = (s[k] < NUM_NODES) && (d[k] < NUM_NODES);
        if (ok[k])
            v[k] = *(reinterpret_cast<const float4*>(feat + (size_t)s[k] * FP) + h);
    }
    #pragma unroll
    for (int k = 0; k < ITEMS_PER_THREAD; k++) {
        if (ok[k])
            red_add_v4(g_agg + (size_t)d[k] * FP + h * 4, v[k]);
    }
}

// ---------------------------------------------------------------------------
// per-node dense transform.
// FINAL=false : write padded h into g_h8, re-zero g_agg for layer 2.
// FINAL=true  : argmax (first-max wins = jnp.argmax) -> one-hot (streaming).
// ---------------------------------------------------------------------------
template <bool FINAL>
__global__ void transform_kernel(const float* __restrict__ Wrel,
                                 const float* __restrict__ Wroot,
                                 const float* __restrict__ b,
                                 float* __restrict__ out) {
    __shared__ float swr[36], swo[36], sb[6];
    int t = threadIdx.x;
    if (t < 36)        swr[t]      = Wrel[t];
    else if (t < 72)   swo[t - 36] = Wroot[t - 36];
    else if (t < 78)   sb[t - 72]  = b[t - 72];
    __syncthreads();

    int i = blockIdx.x * blockDim.x + t;
    if (i >= NUM_NODES) return;

    const float* in_feat = FINAL ? g_h8 : g_x8;

    const float4* pa = reinterpret_cast<const float4*>(g_agg + (size_t)i * FP);
    float4 a0 = __ldcs(pa);     float4 a1 = __ldcs(pa + 1);
    const float4* px = reinterpret_cast<const float4*>(in_feat + (size_t)i * FP);
    float4 x0 = __ldcs(px);     float4 x1 = __ldcs(px + 1);

    float ag[6] = {a0.x, a0.y, a0.z, a0.w, a1.x, a1.y};
    float xv[6] = {x0.x, x0.y, x0.z, x0.w, x1.x, x1.y};

    float h[6];
    #pragma unroll
    for (int k = 0; k < 6; k++) {
        float acc = sb[k];
        #pragma unroll
        for (int j = 0; j < 6; j++) {
            acc = fmaf(ag[j], swr[k * 6 + j], acc);
            acc = fmaf(xv[j], swo[k * 6 + j], acc);
        }
        h[k] = acc;
    }

    if (!FINAL) {
        float4 z = make_float4(0.f, 0.f, 0.f, 0.f);
        float4* paw = reinterpret_cast<float4*>(g_agg + (size_t)i * FP);
        paw[0] = z; paw[1] = z;
        float4* ph = reinterpret_cast<float4*>(g_h8 + (size_t)i * FP);
        ph[0] = make_float4(h[0], h[1], h[2], h[3]);
        ph[1] = make_float4(h[4], h[5], 0.f, 0.f);
    } else {
        int best = 0; float bv = h[0];
        #pragma unroll
        for (int k = 1; k < 6; k++)
            if (h[k] > bv) { bv = h[k]; best = k; }
        // streaming scalar stores: output is never re-read on-device
        float* po = out + (size_t)i * F;
        #pragma unroll
        for (int k = 0; k < 6; k++) {
            float val = (k == best) ? 1.f : 0.f;
            asm volatile("st.global.cs.f32 [%0], %1;" :: "l"(po + k), "f"(val) : "memory");
        }
    }
}

extern "C" void kernel_launch(void* const* d_in, const int* in_sizes, int n_in,
                              void* d_out, int out_size) {
    const float* x      = (const float*)d_in[0];
    const void*  ei     = d_in[1];
    const float* Wrel1  = (const float*)d_in[2];
    const float* Wroot1 = (const float*)d_in[3];
    const float* b1     = (const float*)d_in[4];
    const float* Wrel2  = (const float*)d_in[5];
    const float* Wroot2 = (const float*)d_in[6];
    const float* b2     = (const float*)d_in[7];
    float*       out    = (float*)d_out;

    const int BLK = 256;
    const int node_grid = (NUM_NODES + BLK - 1) / BLK;
    const int pair_grid = (NUM_NODES / 2 + BLK - 1) / BLK;
    const int scat_grid = SCAT_THREADS / BLK;          // exact

    // Layer 1
    prep_kernel<<<pair_grid, BLK>>>(x, (const long long*)ei);
    scatter_kernel<0><<<scat_grid, BLK>>>(ei);
    transform_kernel<false><<<node_grid, BLK>>>(Wrel1, Wroot1, b1, nullptr);
    // Layer 2
    scatter_kernel<1><<<scat_grid, BLK>>>(ei);
    transform_kernel<true><<<node_grid, BLK>>>(Wrel2, Wroot2, b2, out);
}